// round 1
// baseline (speedup 1.0000x reference)
#include <cuda_runtime.h>

// CrossAttMultiplexer collapses analytically:
//   scores[n,i,j] = (WQ.WK)/sqrt(d) * x[n,i] * s[n,j]   (rank-1)
//   alpha = softmax(scores, axis=-1)
//   out[n,i] = v[n,i] * sum_j alpha[n,i,j] = v[n,i] * 1 = s[n,i] * WV[0,0]
// So the whole op is an elementwise scale of s by the scalar WV[0].
// This is a pure HBM-streaming kernel: read s, write out. 12.6 MB total.

__global__ void __launch_bounds__(256, 1)
scale_v4_kernel(const float4* __restrict__ s4,
                const float* __restrict__ WV,
                float4* __restrict__ out4,
                int n4) {
    const float wv = __ldg(WV);  // scalar, L1/L2-resident after first sector
    int i = blockIdx.x * blockDim.x + threadIdx.x;
    if (i < n4) {
        float4 v = s4[i];
        v.x *= wv; v.y *= wv; v.z *= wv; v.w *= wv;
        out4[i] = v;
    }
}

// Tail handler for element counts not divisible by 4 (not expected here:
// 4*64*64*96 = 1,572,864 is divisible by 4, but stay safe).
__global__ void scale_tail_kernel(const float* __restrict__ s,
                                  const float* __restrict__ WV,
                                  float* __restrict__ out,
                                  int start, int n) {
    int i = start + blockIdx.x * blockDim.x + threadIdx.x;
    if (i < n) out[i] = s[i] * WV[0];
}

extern "C" void kernel_launch(void* const* d_in, const int* in_sizes, int n_in,
                              void* d_out, int out_size) {
    // metadata order: x, s, WQ, WK, WV
    const float* s  = (const float*)d_in[1];
    const float* WV = (const float*)d_in[4];
    float* out = (float*)d_out;

    int n  = out_size;          // == b*h*w*c elements
    int n4 = n >> 2;
    if (n4 > 0) {
        int threads = 256;
        int blocks = (n4 + threads - 1) / threads;
        scale_v4_kernel<<<blocks, threads>>>((const float4*)s, WV,
                                             (float4*)out, n4);
    }
    int tail_start = n4 << 2;
    int tail = n - tail_start;
    if (tail > 0) {
        scale_tail_kernel<<<1, 32>>>(s, WV, out, tail_start, n);
    }
}